// round 10
// baseline (speedup 1.0000x reference)
#include <cuda_runtime.h>
#include <cuda_bf16.h>
#include <cstdint>

// ---------------------------------------------------------------------------
// GINConv: out = relu((x + segment_sum(x[src], dst)) @ W1 + b1) @ W2 + b2
// N=50000, E=640000, D=128, fp32, edge_index int32.
//
//   K0: prep_zero - weight bf16 hi/lo split/transpose + zero degree
//   K1: hist      - degree histogram + per-edge rank
//   K2-4: scan1/2/3 - coalesced multi-block exclusive scan (do NOT use a
//         chunk-per-thread single-block scan: R7/R8 showed ~70us of
//         uncoalesced single-SM wavefronts)
//   K5: fill      - CSR fill (sector-bound; atomics vs rank are equivalent)
//   K6: fused     - per 128-row tile: CSR gather (fp32 regs) -> bf16 hi/lo
//                   split into smem -> HMMA GEMM1 -> relu -> GEMM2 -> store.
//                   256 thr / 255 regs (R7: 512 thr spills, 2x regression).
// ---------------------------------------------------------------------------

#define DIM    128
#define MAX_N  50000
#define MAX_E  640000
#define TILE_M 128
#define PA     136                       // padded pitch (elems), 272B rows
#define TBYTES (128 * PA * 2)            // 34816 B per bf16 tile

__device__ int g_deg[MAX_N];
__device__ int g_incl[MAX_N];
__device__ int g_part[64];
__device__ int g_start[MAX_N];
__device__ int g_rank[MAX_E];
__device__ int g_csr[MAX_E];

// W^T hi/lo tiles, [n][k] row-major, pitch PA
__device__ __align__(16) __nv_bfloat16 g_w1h[128 * PA];
__device__ __align__(16) __nv_bfloat16 g_w1l[128 * PA];
__device__ __align__(16) __nv_bfloat16 g_w2h[128 * PA];
__device__ __align__(16) __nv_bfloat16 g_w2l[128 * PA];

__device__ __forceinline__ uint32_t smem_u32(const void* p) {
    uint32_t a;
    asm("{ .reg .u64 t; cvta.to.shared.u64 t, %1; cvt.u32.u64 %0, t; }"
        : "=r"(a) : "l"(p));
    return a;
}
__device__ __forceinline__ void ldmx4(uint32_t addr, uint32_t r[4]) {
    asm volatile("ldmatrix.sync.aligned.m8n8.x4.shared.b16 {%0,%1,%2,%3}, [%4];"
                 : "=r"(r[0]), "=r"(r[1]), "=r"(r[2]), "=r"(r[3]) : "r"(addr));
}
__device__ __forceinline__ void mma16816(float c[4], const uint32_t a[4],
                                         uint32_t b0, uint32_t b1) {
    asm volatile("mma.sync.aligned.m16n8k16.row.col.f32.bf16.bf16.f32 "
                 "{%0,%1,%2,%3}, {%4,%5,%6,%7}, {%8,%9}, {%0,%1,%2,%3};"
                 : "+f"(c[0]), "+f"(c[1]), "+f"(c[2]), "+f"(c[3])
                 : "r"(a[0]), "r"(a[1]), "r"(a[2]), "r"(a[3]), "r"(b0), "r"(b1));
}
__device__ __forceinline__ void bf16_split(float a, __nv_bfloat16& h, __nv_bfloat16& l) {
    h = __float2bfloat16_rn(a);
    l = __float2bfloat16_rn(a - __bfloat162float(h));
}
__device__ __forceinline__ uint32_t pack_bf2(__nv_bfloat16 a, __nv_bfloat16 b) {
    __nv_bfloat162 t(a, b);
    return *reinterpret_cast<uint32_t*>(&t);
}

// ---------------------------------------------------------------------------
// K0: weight split/transpose + zero degree counters
// ---------------------------------------------------------------------------
__global__ void prep_zero(const float* __restrict__ W1,
                          const float* __restrict__ W2, int N) {
    int idx = blockIdx.x * blockDim.x + threadIdx.x;
    if (idx < DIM * DIM) {
        int k = idx >> 7, n = idx & 127;
        int o = n * PA + k;
        __nv_bfloat16 h, l;
        bf16_split(W1[idx], h, l);
        g_w1h[o] = h; g_w1l[o] = l;
        bf16_split(W2[idx], h, l);
        g_w2h[o] = h; g_w2l[o] = l;
    }
    if (idx < N) g_deg[idx] = 0;
}

// K1: degree histogram + per-edge rank
__global__ void hist_kernel(const int* __restrict__ ei, int E) {
    int e = blockIdx.x * blockDim.x + threadIdx.x;
    if (e >= E) return;
    g_rank[e] = atomicAdd(&g_deg[ei[E + e]], 1);
}

// K2: per-chunk inclusive scan (1024 elems/block, coalesced)
__global__ void scan1_kernel(int N) {
    __shared__ int s[1024];
    int tid = threadIdx.x;
    int idx = blockIdx.x * 1024 + tid;
    int v = (idx < N) ? g_deg[idx] : 0;
    s[tid] = v;
    __syncthreads();
    #pragma unroll
    for (int off = 1; off < 1024; off <<= 1) {
        int t = (tid >= off) ? s[tid - off] : 0;
        __syncthreads();
        s[tid] += t;
        __syncthreads();
    }
    if (idx < N) g_incl[idx] = s[tid];
    if (tid == 1023) g_part[blockIdx.x] = s[1023];
}

// K3: scan chunk partials (single block, 64 threads)
__global__ void scan2_kernel(int nb) {
    __shared__ int s[64];
    int tid = threadIdx.x;
    int v = (tid < nb) ? g_part[tid] : 0;
    int orig = v;
    s[tid] = v;
    __syncthreads();
    #pragma unroll
    for (int off = 1; off < 64; off <<= 1) {
        int t = (tid >= off) ? s[tid - off] : 0;
        __syncthreads();
        s[tid] += t;
        __syncthreads();
    }
    if (tid < nb) g_part[tid] = s[tid] - orig;   // exclusive
}

// K4: finalize row starts
__global__ void scan3_kernel(int N) {
    int idx = blockIdx.x * blockDim.x + threadIdx.x;
    if (idx >= N) return;
    g_start[idx] = g_incl[idx] + g_part[idx >> 10] - g_deg[idx];
}

// K5: CSR fill (atomic-free; sector-bound either way)
__global__ void fill_kernel(const int* __restrict__ ei, int E) {
    int e = blockIdx.x * blockDim.x + threadIdx.x;
    if (e >= E) return;
    int src = ei[e];
    int dst = ei[E + e];
    g_csr[g_start[dst] + g_rank[e]] = src;
}

// ---------------------------------------------------------------------------
// K6: fused gather + HMMA MLP. 256 threads / 8 warps, 4(m) x 2(n) warp tiles.
// smem: b1s | b2s | Ah | Al | W1h | W1l | W2h | W2l
// ---------------------------------------------------------------------------
#define SM_AH   1024
#define SM_AL   (SM_AH  + TBYTES)
#define SM_W1H  (SM_AL  + TBYTES)
#define SM_W1L  (SM_W1H + TBYTES)
#define SM_W2H  (SM_W1L + TBYTES)
#define SM_W2L  (SM_W2H + TBYTES)
#define SM_TOT  (SM_W2L + TBYTES)

__device__ __forceinline__ void do_gemm(const uint32_t aH[2], const uint32_t aL[2],
                                        uint32_t wH, uint32_t wL,
                                        float (*acc)[4]) {
    #pragma unroll
    for (int k = 0; k < 8; k++) {
        uint32_t ah[2][4], al[2][4];
        #pragma unroll
        for (int im = 0; im < 2; im++) {
            ldmx4(aH[im] + k * 32, ah[im]);
            ldmx4(aL[im] + k * 32, al[im]);
        }
        #pragma unroll
        for (int jn = 0; jn < 4; jn++) {
            uint32_t boff = (uint32_t)(jn * 16 * PA * 2 + k * 32);
            uint32_t bh[4], bl[4];
            ldmx4(wH + boff, bh);
            ldmx4(wL + boff, bl);
            #pragma unroll
            for (int im = 0; im < 2; im++) {
                float* c0 = acc[im * 8 + jn * 2];
                float* c1 = acc[im * 8 + jn * 2 + 1];
                mma16816(c0, ah[im], bh[0], bh[1]);
                mma16816(c0, ah[im], bl[0], bl[1]);
                mma16816(c0, al[im], bh[0], bh[1]);
                mma16816(c1, ah[im], bh[2], bh[3]);
                mma16816(c1, ah[im], bl[2], bl[3]);
                mma16816(c1, al[im], bh[2], bh[3]);
            }
        }
    }
}

__global__ void __launch_bounds__(256, 1)
fused_kernel(const float4* __restrict__ x4,
             const float* __restrict__ b1,
             const float* __restrict__ b2,
             float* __restrict__ out, int M) {
    extern __shared__ unsigned char sm[];
    const uint32_t sb = smem_u32(sm);
    const int tid  = threadIdx.x;
    const int w    = tid >> 5;
    const int lane = tid & 31;
    const int wm   = w >> 1;          // 0..3
    const int wn   = w & 1;           // 0..1
    const int rowBase = blockIdx.x * TILE_M;

    float* b1s = reinterpret_cast<float*>(sm);
    float* b2s = reinterpret_cast<float*>(sm + 512);
    if (tid < DIM) {
        b1s[tid] = b1[tid];
        b2s[tid] = b2[tid];
    }

    // weight tiles (linear coalesced copy; overlaps with gather issue below)
    {
        const uint4* s1h = reinterpret_cast<const uint4*>(g_w1h);
        const uint4* s1l = reinterpret_cast<const uint4*>(g_w1l);
        const uint4* s2h = reinterpret_cast<const uint4*>(g_w2h);
        const uint4* s2l = reinterpret_cast<const uint4*>(g_w2l);
        uint4* d1h = reinterpret_cast<uint4*>(sm + SM_W1H);
        uint4* d1l = reinterpret_cast<uint4*>(sm + SM_W1L);
        uint4* d2h = reinterpret_cast<uint4*>(sm + SM_W2H);
        uint4* d2l = reinterpret_cast<uint4*>(sm + SM_W2L);
        for (int i = tid; i < TBYTES / 16; i += 256) {
            d1h[i] = s1h[i]; d1l[i] = s1l[i];
            d2h[i] = s2h[i]; d2l[i] = s2l[i];
        }
    }

    // --- fused gather: warp handles 16 nodes; lane owns float4 chunk ---
    {
        uint32_t* Ah2 = reinterpret_cast<uint32_t*>(sm + SM_AH);
        uint32_t* Al2 = reinterpret_cast<uint32_t*>(sm + SM_AL);
        for (int i = 0; i < 16; i++) {
            int m  = w * 16 + i;
            int gm = rowBase + m;
            float4 acc = make_float4(0.f, 0.f, 0.f, 0.f);
            if (gm < M) {
                acc = x4[(size_t)gm * 32 + lane];
                int j   = g_start[gm];
                int end = j + g_deg[gm];
                #pragma unroll 4
                for (; j < end; j++) {
                    float4 a = x4[(size_t)g_csr[j] * 32 + lane];
                    acc.x += a.x; acc.y += a.y; acc.z += a.z; acc.w += a.w;
                }
            }
            __nv_bfloat16 h0, l0, h1, l1, h2, l2, h3, l3;
            bf16_split(acc.x, h0, l0);
            bf16_split(acc.y, h1, l1);
            bf16_split(acc.z, h2, l2);
            bf16_split(acc.w, h3, l3);
            // 4 bf16 = 2 words; base elem = m*PA + lane*4 (word-aligned)
            int wb = (m * PA + lane * 4) >> 1;
            Ah2[wb]     = pack_bf2(h0, h1);
            Ah2[wb + 1] = pack_bf2(h2, h3);
            Al2[wb]     = pack_bf2(l0, l1);
            Al2[wb + 1] = pack_bf2(l2, l3);
        }
    }
    __syncthreads();

    // ldmatrix lane addressing
    uint32_t aH[2], aL[2];
    #pragma unroll
    for (int im = 0; im < 2; im++) {
        uint32_t off = (uint32_t)(((wm * 32 + im * 16 + (lane & 15)) * PA
                                   + ((lane >> 4) << 3)) * 2);
        aH[im] = sb + SM_AH + off;
        aL[im] = sb + SM_AL + off;
    }
    const uint32_t bLaneOff =
        (uint32_t)((((lane & 7) + ((lane >> 4) << 3) + wn * 64) * PA
                    + (((lane >> 3) & 1) << 3)) * 2);

    float acc[16][4];
    #pragma unroll
    for (int i = 0; i < 16; i++)
        #pragma unroll
        for (int j = 0; j < 4; j++) acc[i][j] = 0.f;

    // ---- GEMM1 ----
    do_gemm(aH, aL, sb + SM_W1H + bLaneOff, sb + SM_W1L + bLaneOff, acc);

    // ---- epilogue 1: +b1, relu, split -> H into Ah/Al ----
    {
        __nv_bfloat16* Ah = reinterpret_cast<__nv_bfloat16*>(sm + SM_AH);
        __nv_bfloat16* Al = reinterpret_cast<__nv_bfloat16*>(sm + SM_AL);
        #pragma unroll
        for (int im = 0; im < 2; im++) {
            int r0 = wm * 32 + im * 16 + (lane >> 2);
            int r1 = r0 + 8;
            #pragma unroll
            for (int jn = 0; jn < 4; jn++) {
                #pragma unroll
                for (int h = 0; h < 2; h++) {
                    float* c = acc[im * 8 + jn * 2 + h];
                    int n = wn * 64 + jn * 16 + h * 8 + 2 * (lane & 3);
                    float f00 = c[0] + b1s[n];
                    float f01 = c[1] + b1s[n + 1];
                    float f10 = c[2] + b1s[n];
                    float f11 = c[3] + b1s[n + 1];
                    f00 = f00 > 0.f ? f00 : 0.f;  f01 = f01 > 0.f ? f01 : 0.f;
                    f10 = f10 > 0.f ? f10 : 0.f;  f11 = f11 > 0.f ? f11 : 0.f;
                    __nv_bfloat16 hh, ll;
                    bf16_split(f00, hh, ll); Ah[r0*PA + n]   = hh; Al[r0*PA + n]   = ll;
                    bf16_split(f01, hh, ll); Ah[r0*PA + n+1] = hh; Al[r0*PA + n+1] = ll;
                    bf16_split(f10, hh, ll); Ah[r1*PA + n]   = hh; Al[r1*PA + n]   = ll;
                    bf16_split(f11, hh, ll); Ah[r1*PA + n+1] = hh; Al[r1*PA + n+1] = ll;
                    c[0] = c[1] = c[2] = c[3] = 0.f;
                }
            }
        }
    }
    __syncthreads();

    // ---- GEMM2 ----
    do_gemm(aH, aL, sb + SM_W2H + bLaneOff, sb + SM_W2L + bLaneOff, acc);

    // ---- epilogue 2: +b2, store fp32 ----
    #pragma unroll
    for (int im = 0; im < 2; im++) {
        int gm0 = rowBase + wm * 32 + im * 16 + (lane >> 2);
        int gm1 = gm0 + 8;
        #pragma unroll
        for (int jn = 0; jn < 4; jn++) {
            #pragma unroll
            for (int h = 0; h < 2; h++) {
                float* c = acc[im * 8 + jn * 2 + h];
                int n = wn * 64 + jn * 16 + h * 8 + 2 * (lane & 3);
                if (gm0 < M) {
                    float2 o = make_float2(c[0] + b2s[n], c[1] + b2s[n + 1]);
                    *reinterpret_cast<float2*>(&out[(size_t)gm0 * DIM + n]) = o;
                }
                if (gm1 < M) {
                    float2 o = make_float2(c[2] + b2s[n], c[3] + b2s[n + 1]);
                    *reinterpret_cast<float2*>(&out[(size_t)gm1 * DIM + n]) = o;
                }
            }
        }
    }
}

// ---------------------------------------------------------------------------
// launch
// ---------------------------------------------------------------------------
extern "C" void kernel_launch(void* const* d_in, const int* in_sizes, int n_in,
                              void* d_out, int out_size) {
    const float* x   = (const float*)d_in[0];
    const int*   ei  = (const int*)d_in[1];
    const float* W1  = (const float*)d_in[2];
    const float* b1  = (const float*)d_in[3];
    const float* W2  = (const float*)d_in[4];
    const float* b2  = (const float*)d_in[5];
    float*       out = (float*)d_out;

    const int M = in_sizes[0] / DIM;   // 50000
    const int E = in_sizes[1] / 2;     // 640000
    const int nChunks = (M + 1023) / 1024;

    prep_zero<<<(M + 255) / 256, 256>>>(W1, W2, M);
    hist_kernel<<<(E + 255) / 256, 256>>>(ei, E);
    scan1_kernel<<<nChunks, 1024>>>(M);
    scan2_kernel<<<1, 64>>>(nChunks);
    scan3_kernel<<<(M + 255) / 256, 256>>>(M);
    fill_kernel<<<(E + 255) / 256, 256>>>(ei, E);

    cudaFuncSetAttribute(fused_kernel,
                         cudaFuncAttributeMaxDynamicSharedMemorySize, SM_TOT);
    fused_kernel<<<(M + TILE_M - 1) / TILE_M, 256, SM_TOT>>>(
        reinterpret_cast<const float4*>(x), b1, b2, out, M);
}

// round 11
// speedup vs baseline: 1.6513x; 1.6513x over previous
#include <cuda_runtime.h>
#include <cuda_bf16.h>
#include <cstdint>

// ---------------------------------------------------------------------------
// GINConv: out = relu((x + segment_sum(x[src], dst)) @ W1 + b1) @ W2 + b2
// N=50000, E=640000, D=128, fp32, edge_index int32.
//
//   K0: prep_zero - weight bf16 hi/lo split/transpose + zero degree
//   K1: hist      - degree histogram + per-edge rank
//   K2: scan1     - per-1024-chunk inclusive scan (coalesced)
//   K3: scan3     - row starts; chunk-prefix (<=49 elems) computed inline
//                   (replaces the separate scan2 launch: 4us pure overhead)
//   K4: fill      - atomic-free CSR fill via start[dst] + rank[e]
//   K5: gather    - agg = x + sum x[src]  (warp/node; separate kernel ON
//                   PURPOSE: fusing into the MLP drops gather to 8 warps/SM
//                   and cost +57us in R10)
//   K6: mlp       - HMMA bf16x3 split, 256 thr / 255 regs, 4(m)x2(n) warps
//                   (512 thr spills and 2x-regresses: R7)
// ---------------------------------------------------------------------------

#define DIM    128
#define MAX_N  50000
#define MAX_E  640000
#define TILE_M 128
#define PA     136                       // padded pitch (elems), 272B rows
#define TBYTES (128 * PA * 2)            // 34816 B per bf16 tile

__device__ float g_agg[MAX_N * DIM];

__device__ int g_deg[MAX_N];
__device__ int g_incl[MAX_N];
__device__ int g_part[64];
__device__ int g_start[MAX_N];
__device__ int g_rank[MAX_E];
__device__ int g_csr[MAX_E];

// W^T hi/lo tiles, [n][k] row-major, pitch PA
__device__ __align__(16) __nv_bfloat16 g_w1h[128 * PA];
__device__ __align__(16) __nv_bfloat16 g_w1l[128 * PA];
__device__ __align__(16) __nv_bfloat16 g_w2h[128 * PA];
__device__ __align__(16) __nv_bfloat16 g_w2l[128 * PA];

__device__ __forceinline__ uint32_t smem_u32(const void* p) {
    uint32_t a;
    asm("{ .reg .u64 t; cvta.to.shared.u64 t, %1; cvt.u32.u64 %0, t; }"
        : "=r"(a) : "l"(p));
    return a;
}
__device__ __forceinline__ void ldmx4(uint32_t addr, uint32_t r[4]) {
    asm volatile("ldmatrix.sync.aligned.m8n8.x4.shared.b16 {%0,%1,%2,%3}, [%4];"
                 : "=r"(r[0]), "=r"(r[1]), "=r"(r[2]), "=r"(r[3]) : "r"(addr));
}
__device__ __forceinline__ void mma16816(float c[4], const uint32_t a[4],
                                         uint32_t b0, uint32_t b1) {
    asm volatile("mma.sync.aligned.m16n8k16.row.col.f32.bf16.bf16.f32 "
                 "{%0,%1,%2,%3}, {%4,%5,%6,%7}, {%8,%9}, {%0,%1,%2,%3};"
                 : "+f"(c[0]), "+f"(c[1]), "+f"(c[2]), "+f"(c[3])
                 : "r"(a[0]), "r"(a[1]), "r"(a[2]), "r"(a[3]), "r"(b0), "r"(b1));
}
__device__ __forceinline__ void bf16_split(float a, __nv_bfloat16& h, __nv_bfloat16& l) {
    h = __float2bfloat16_rn(a);
    l = __float2bfloat16_rn(a - __bfloat162float(h));
}

// ---------------------------------------------------------------------------
// K0: weight split/transpose + zero degree counters
// ---------------------------------------------------------------------------
__global__ void prep_zero(const float* __restrict__ W1,
                          const float* __restrict__ W2, int N) {
    int idx = blockIdx.x * blockDim.x + threadIdx.x;
    if (idx < DIM * DIM) {
        int k = idx >> 7, n = idx & 127;
        int o = n * PA + k;
        __nv_bfloat16 h, l;
        bf16_split(W1[idx], h, l);
        g_w1h[o] = h; g_w1l[o] = l;
        bf16_split(W2[idx], h, l);
        g_w2h[o] = h; g_w2l[o] = l;
    }
    if (idx < N) g_deg[idx] = 0;
}

// K1: degree histogram + per-edge rank
__global__ void hist_kernel(const int* __restrict__ ei, int E) {
    int e = blockIdx.x * blockDim.x + threadIdx.x;
    if (e >= E) return;
    g_rank[e] = atomicAdd(&g_deg[ei[E + e]], 1);
}

// K2: per-chunk inclusive scan (1024 elems/block, coalesced)
__global__ void scan1_kernel(int N) {
    __shared__ int s[1024];
    int tid = threadIdx.x;
    int idx = blockIdx.x * 1024 + tid;
    int v = (idx < N) ? g_deg[idx] : 0;
    s[tid] = v;
    __syncthreads();
    #pragma unroll
    for (int off = 1; off < 1024; off <<= 1) {
        int t = (tid >= off) ? s[tid - off] : 0;
        __syncthreads();
        s[tid] += t;
        __syncthreads();
    }
    if (idx < N) g_incl[idx] = s[tid];
    if (tid == 1023) g_part[blockIdx.x] = s[1023];   // chunk total
}

// K3: row starts; per-block chunk-prefix computed inline (nChunks <= 64)
__global__ void scan3_kernel(int N, int nChunks) {
    __shared__ int sbase[2];
    int blk0 = blockIdx.x * blockDim.x;
    int c0   = blk0 >> 10;
    if (threadIdx.x < 2) {
        int c = c0 + threadIdx.x;
        int s = 0;
        for (int i = 0; i < c && i < nChunks; i++) s += g_part[i];
        sbase[threadIdx.x] = s;     // exclusive prefix of chunk c
    }
    __syncthreads();
    int idx = blk0 + threadIdx.x;
    if (idx >= N) return;
    g_start[idx] = g_incl[idx] + sbase[(idx >> 10) - c0] - g_deg[idx];
}

// K4: atomic-free CSR fill
__global__ void fill_kernel(const int* __restrict__ ei, int E) {
    int e = blockIdx.x * blockDim.x + threadIdx.x;
    if (e >= E) return;
    int src = ei[e];
    int dst = ei[E + e];
    g_csr[g_start[dst] + g_rank[e]] = src;
}

// K5: gather-sum. One warp per node: agg[i] = x[i] + sum_j x[csr[j]]
__global__ void gather_kernel(const float4* __restrict__ x4, int N) {
    int node = blockIdx.x * 8 + (threadIdx.x >> 5);
    int lane = threadIdx.x & 31;
    if (node >= N) return;

    float4 acc = x4[(size_t)node * 32 + lane];
    int j   = g_start[node];
    int end = j + g_deg[node];
    for (; j + 1 < end; j += 2) {
        int s0 = g_csr[j];
        int s1 = g_csr[j + 1];
        float4 a = x4[(size_t)s0 * 32 + lane];
        float4 b = x4[(size_t)s1 * 32 + lane];
        acc.x += a.x; acc.y += a.y; acc.z += a.z; acc.w += a.w;
        acc.x += b.x; acc.y += b.y; acc.z += b.z; acc.w += b.w;
    }
    if (j < end) {
        float4 a = x4[(size_t)g_csr[j] * 32 + lane];
        acc.x += a.x; acc.y += a.y; acc.z += a.z; acc.w += a.w;
    }
    reinterpret_cast<float4*>(g_agg)[(size_t)node * 32 + lane] = acc;
}

// ---------------------------------------------------------------------------
// K6: HMMA MLP. 256 threads / 8 warps tiled 4(m) x 2(n): warp owns 32x64.
// smem: b1s | b2s | Ah | Al | W1h | W1l | W2h | W2l
// ---------------------------------------------------------------------------
#define SM_AH   1024
#define SM_AL   (SM_AH  + TBYTES)
#define SM_W1H  (SM_AL  + TBYTES)
#define SM_W1L  (SM_W1H + TBYTES)
#define SM_W2H  (SM_W1L + TBYTES)
#define SM_W2L  (SM_W2H + TBYTES)
#define SM_TOT  (SM_W2L + TBYTES)

// acc layout: acc[im*8 + jn*2 + h][4]
__device__ __forceinline__ void do_gemm(const uint32_t aH[2], const uint32_t aL[2],
                                        uint32_t wH, uint32_t wL,
                                        float (*acc)[4]) {
    #pragma unroll
    for (int k = 0; k < 8; k++) {
        uint32_t ah[2][4], al[2][4];
        #pragma unroll
        for (int im = 0; im < 2; im++) {
            ldmx4(aH[im] + k * 32, ah[im]);
            ldmx4(aL[im] + k * 32, al[im]);
        }
        #pragma unroll
        for (int jn = 0; jn < 4; jn++) {
            uint32_t boff = (uint32_t)(jn * 16 * PA * 2 + k * 32);
            uint32_t bh[4], bl[4];
            ldmx4(wH + boff, bh);
            ldmx4(wL + boff, bl);
            #pragma unroll
            for (int im = 0; im < 2; im++) {
                float* c0 = acc[im * 8 + jn * 2];
                float* c1 = acc[im * 8 + jn * 2 + 1];
                mma16816(c0, ah[im], bh[0], bh[1]);
                mma16816(c0, ah[im], bl[0], bl[1]);
                mma16816(c0, al[im], bh[0], bh[1]);
                mma16816(c1, ah[im], bh[2], bh[3]);
                mma16816(c1, ah[im], bl[2], bl[3]);
                mma16816(c1, al[im], bh[2], bh[3]);
            }
        }
    }
}

__global__ void __launch_bounds__(256, 1)
mlp_hmma_kernel(const float* __restrict__ b1,
                const float* __restrict__ b2,
                float* __restrict__ out, int M) {
    extern __shared__ unsigned char sm[];
    const uint32_t sb = smem_u32(sm);
    const int tid  = threadIdx.x;
    const int w    = tid >> 5;
    const int lane = tid & 31;
    const int wm   = w >> 1;          // 0..3
    const int wn   = w & 1;           // 0..1
    const int rowBase = blockIdx.x * TILE_M;

    float* b1s = reinterpret_cast<float*>(sm);
    float* b2s = reinterpret_cast<float*>(sm + 512);
    if (tid < DIM) {
        b1s[tid] = b1[tid];
        b2s[tid] = b2[tid];
    }

    // weight tiles (linear coalesced copy)
    {
        const uint4* s1h = reinterpret_cast<const uint4*>(g_w1h);
        const uint4* s1l = reinterpret_cast<const uint4*>(g_w1l);
        const uint4* s2h = reinterpret_cast<const uint4*>(g_w2h);
        const uint4* s2l = reinterpret_cast<const uint4*>(g_w2l);
        uint4* d1h = reinterpret_cast<uint4*>(sm + SM_W1H);
        uint4* d1l = reinterpret_cast<uint4*>(sm + SM_W1L);
        uint4* d2h = reinterpret_cast<uint4*>(sm + SM_W2H);
        uint4* d2l = reinterpret_cast<uint4*>(sm + SM_W2L);
        for (int i = tid; i < TBYTES / 16; i += 256) {
            d1h[i] = s1h[i]; d1l[i] = s1l[i];
            d2h[i] = s2h[i]; d2l[i] = s2l[i];
        }
    }

    // A tile: load agg rows, split bf16 hi/lo, [m][k] pitch PA
    {
        __nv_bfloat16* Ah = reinterpret_cast<__nv_bfloat16*>(sm + SM_AH);
        __nv_bfloat16* Al = reinterpret_cast<__nv_bfloat16*>(sm + SM_AL);
        const float4* in4 = reinterpret_cast<const float4*>(g_agg);
        #pragma unroll
        for (int i = tid; i < TILE_M * 32; i += 256) {
            int m = i >> 5, c = i & 31;
            int gm = rowBase + m;
            float4 v = make_float4(0.f, 0.f, 0.f, 0.f);
            if (gm < M) v = in4[(size_t)gm * 32 + c];
            float vv[4] = {v.x, v.y, v.z, v.w};
            #pragma unroll
            for (int j = 0; j < 4; j++) {
                __nv_bfloat16 h, l;
                bf16_split(vv[j], h, l);
                Ah[m * PA + c * 4 + j] = h;
                Al[m * PA + c * 4 + j] = l;
            }
        }
    }
    __syncthreads();

    // ldmatrix lane addressing
    uint32_t aH[2], aL[2];
    #pragma unroll
    for (int im = 0; im < 2; im++) {
        uint32_t off = (uint32_t)(((wm * 32 + im * 16 + (lane & 15)) * PA
                                   + ((lane >> 4) << 3)) * 2);
        aH[im] = sb + SM_AH + off;
        aL[im] = sb + SM_AL + off;
    }
    const uint32_t bLaneOff =
        (uint32_t)((((lane & 7) + ((lane >> 4) << 3) + wn * 64) * PA
                    + (((lane >> 3) & 1) << 3)) * 2);

    float acc[16][4];
    #pragma unroll
    for (int i = 0; i < 16; i++)
        #pragma unroll
        for (int j = 0; j < 4; j++) acc[i][j] = 0.f;

    // ---- GEMM1 ----
    do_gemm(aH, aL, sb + SM_W1H + bLaneOff, sb + SM_W1L + bLaneOff, acc);

    // ---- epilogue 1: +b1, relu, split -> H into Ah/Al ----
    {
        __nv_bfloat16* Ah = reinterpret_cast<__nv_bfloat16*>(sm + SM_AH);
        __nv_bfloat16* Al = reinterpret_cast<__nv_bfloat16*>(sm + SM_AL);
        #pragma unroll
        for (int im = 0; im < 2; im++) {
            int r0 = wm * 32 + im * 16 + (lane >> 2);
            int r1 = r0 + 8;
            #pragma unroll
            for (int jn = 0; jn < 4; jn++) {
                #pragma unroll
                for (int h = 0; h < 2; h++) {
                    float* c = acc[im * 8 + jn * 2 + h];
                    int n = wn * 64 + jn * 16 + h * 8 + 2 * (lane & 3);
                    float f00 = c[0] + b1s[n];
                    float f01 = c[1] + b1s[n + 1];
                    float f10 = c[2] + b1s[n];
                    float f11 = c[3] + b1s[n + 1];
                    f00 = f00 > 0.f ? f00 : 0.f;  f01 = f01 > 0.f ? f01 : 0.f;
                    f10 = f10 > 0.f ? f10 : 0.f;  f11 = f11 > 0.f ? f11 : 0.f;
                    __nv_bfloat16 hh, ll;
                    bf16_split(f00, hh, ll); Ah[r0*PA + n]   = hh; Al[r0*PA + n]   = ll;
                    bf16_split(f01, hh, ll); Ah[r0*PA + n+1] = hh; Al[r0*PA + n+1] = ll;
                    bf16_split(f10, hh, ll); Ah[r1*PA + n]   = hh; Al[r1*PA + n]   = ll;
                    bf16_split(f11, hh, ll); Ah[r1*PA + n+1] = hh; Al[r1*PA + n+1] = ll;
                    c[0] = c[1] = c[2] = c[3] = 0.f;
                }
            }
        }
    }
    __syncthreads();   // H cols of a row written by both n-warps

    // ---- GEMM2 ----
    do_gemm(aH, aL, sb + SM_W2H + bLaneOff, sb + SM_W2L + bLaneOff, acc);

    // ---- epilogue 2: +b2, store fp32 ----
    #pragma unroll
    for (int im = 0; im < 2; im++) {
        int gm0 = rowBase + wm * 32 + im * 16 + (lane >> 2);
        int gm1 = gm0 + 8;
        #pragma unroll
        for (int jn = 0; jn < 4; jn++) {
            #pragma unroll
            for (int h = 0; h < 2; h++) {
                float* c = acc[im * 8 + jn * 2 + h];
                int n = wn * 64 + jn * 16 + h * 8 + 2 * (lane & 3);
                if (gm0 < M) {
                    float2 o = make_float2(c[0] + b2s[n], c[1] + b2s[n + 1]);
                    *reinterpret_cast<float2*>(&out[(size_t)gm0 * DIM + n]) = o;
                }
                if (gm1 < M) {
                    float2 o = make_float2(c[2] + b2s[n], c[3] + b2s[n + 1]);
                    *reinterpret_cast<float2*>(&out[(size_t)gm1 * DIM + n]) = o;
                }
            }
        }
    }
}

// ---------------------------------------------------------------------------
// launch
// ---------------------------------------------------------------------------
extern "C" void kernel_launch(void* const* d_in, const int* in_sizes, int n_in,
                              void* d_out, int out_size) {
    const float* x   = (const float*)d_in[0];
    const int*   ei  = (const int*)d_in[1];
    const float* W1  = (const float*)d_in[2];
    const float* b1  = (const float*)d_in[3];
    const float* W2  = (const float*)d_in[4];
    const float* b2  = (const float*)d_in[5];
    float*       out = (float*)d_out;

    const int M = in_sizes[0] / DIM;   // 50000
    const int E = in_sizes[1] / 2;     // 640000
    const int nChunks = (M + 1023) / 1024;

    prep_zero<<<(M + 255) / 256, 256>>>(W1, W2, M);
    hist_kernel<<<(E + 255) / 256, 256>>>(ei, E);
    scan1_kernel<<<nChunks, 1024>>>(M);
    scan3_kernel<<<(M + 255) / 256, 256>>>(M, nChunks);
    fill_kernel<<<(E + 255) / 256, 256>>>(ei, E);
    gather_kernel<<<(M + 7) / 8, 256>>>(
        reinterpret_cast<const float4*>(x), M);

    cudaFuncSetAttribute(mlp_hmma_kernel,
                         cudaFuncAttributeMaxDynamicSharedMemorySize, SM_TOT);
    mlp_hmma_kernel<<<(M + TILE_M - 1) / TILE_M, 256, SM_TOT>>>(b1, b2, out, M);
}

// round 12
// speedup vs baseline: 1.7052x; 1.0326x over previous
#include <cuda_runtime.h>
#include <cuda_bf16.h>
#include <cstdint>

// ---------------------------------------------------------------------------
// GINConv: out = relu((x + segment_sum(x[src], dst)) @ W1 + b1) @ W2 + b2
// N=50000, E=640000, D=128, fp32, edge_index int32. 5 launches.
//
//   K1: hist   - deg histogram + per-edge rank; also weight bf16 split and
//                g_base zeroing (free riders on the 640k-thread grid).
//                deg starts zero: module-load zero-init on call 1, reset by
//                gather at the end of every call thereafter.
//   K2: scan1  - per-1024-chunk scan -> g_exc (in-chunk exclusive) and
//                cross-chunk bases via atomicAdd to g_base[c>b] (<=48 REDG).
//   K3: fill   - csr[g_exc[dst] + g_base[dst>>10] + rank[e]] = src
//   K4: gather - agg = x + sum x[csr]; resets g_deg[node]=0 (last reader).
//                Separate kernel ON PURPOSE: fusing into MLP drops gather to
//                8 warps/SM (+57us, R10).
//   K5: mlp    - HMMA bf16x3, 256 thr / 255 regs, 4(m)x2(n) warps
//                (512 thr spills, 2x regression: R7)
// ---------------------------------------------------------------------------

#define DIM    128
#define MAX_N  50000
#define MAX_E  640000
#define TILE_M 128
#define PA     136                       // padded pitch (elems), 272B rows
#define TBYTES (128 * PA * 2)            // 34816 B per bf16 tile

__device__ float g_agg[MAX_N * DIM];

__device__ int g_deg[MAX_N];             // zero-init at load; gather resets
__device__ int g_exc[MAX_N];
__device__ int g_base[64];
__device__ int g_rank[MAX_E];
__device__ int g_csr[MAX_E];

// W^T hi/lo tiles, [n][k] row-major, pitch PA
__device__ __align__(16) __nv_bfloat16 g_w1h[128 * PA];
__device__ __align__(16) __nv_bfloat16 g_w1l[128 * PA];
__device__ __align__(16) __nv_bfloat16 g_w2h[128 * PA];
__device__ __align__(16) __nv_bfloat16 g_w2l[128 * PA];

__device__ __forceinline__ uint32_t smem_u32(const void* p) {
    uint32_t a;
    asm("{ .reg .u64 t; cvta.to.shared.u64 t, %1; cvt.u32.u64 %0, t; }"
        : "=r"(a) : "l"(p));
    return a;
}
__device__ __forceinline__ void ldmx4(uint32_t addr, uint32_t r[4]) {
    asm volatile("ldmatrix.sync.aligned.m8n8.x4.shared.b16 {%0,%1,%2,%3}, [%4];"
                 : "=r"(r[0]), "=r"(r[1]), "=r"(r[2]), "=r"(r[3]) : "r"(addr));
}
__device__ __forceinline__ void mma16816(float c[4], const uint32_t a[4],
                                         uint32_t b0, uint32_t b1) {
    asm volatile("mma.sync.aligned.m16n8k16.row.col.f32.bf16.bf16.f32 "
                 "{%0,%1,%2,%3}, {%4,%5,%6,%7}, {%8,%9}, {%0,%1,%2,%3};"
                 : "+f"(c[0]), "+f"(c[1]), "+f"(c[2]), "+f"(c[3])
                 : "r"(a[0]), "r"(a[1]), "r"(a[2]), "r"(a[3]), "r"(b0), "r"(b1));
}
__device__ __forceinline__ void bf16_split(float a, __nv_bfloat16& h, __nv_bfloat16& l) {
    h = __float2bfloat16_rn(a);
    l = __float2bfloat16_rn(a - __bfloat162float(h));
}

// ---------------------------------------------------------------------------
// K1: hist + weight prep + g_base zero
// ---------------------------------------------------------------------------
__global__ void hist_kernel(const int* __restrict__ ei, int E,
                            const float* __restrict__ W1,
                            const float* __restrict__ W2) {
    int e = blockIdx.x * blockDim.x + threadIdx.x;
    if (e < DIM * DIM) {
        int k = e >> 7, n = e & 127;
        int o = n * PA + k;
        __nv_bfloat16 h, l;
        bf16_split(W1[e], h, l);
        g_w1h[o] = h; g_w1l[o] = l;
        bf16_split(W2[e], h, l);
        g_w2h[o] = h; g_w2l[o] = l;
    }
    if (e < 64) g_base[e] = 0;
    if (e < E) g_rank[e] = atomicAdd(&g_deg[ei[E + e]], 1);
}

// ---------------------------------------------------------------------------
// K2: per-chunk scan -> g_exc; chunk totals broadcast via atomics to g_base
// ---------------------------------------------------------------------------
__global__ void scan1_kernel(int N, int nChunks) {
    __shared__ int s[1024];
    int tid = threadIdx.x;
    int idx = blockIdx.x * 1024 + tid;
    int v = (idx < N) ? g_deg[idx] : 0;
    s[tid] = v;
    __syncthreads();
    #pragma unroll
    for (int off = 1; off < 1024; off <<= 1) {
        int t = (tid >= off) ? s[tid - off] : 0;
        __syncthreads();
        s[tid] += t;
        __syncthreads();
    }
    if (idx < N) g_exc[idx] = s[tid] - v;          // exclusive within chunk
    if (tid == 1023) {
        int tot = s[1023];                          // chunk total
        for (int c = blockIdx.x + 1; c < nChunks; c++)
            atomicAdd(&g_base[c], tot);
    }
}

// ---------------------------------------------------------------------------
// K3: CSR fill (atomic-free)
// ---------------------------------------------------------------------------
__global__ void fill_kernel(const int* __restrict__ ei, int E) {
    int e = blockIdx.x * blockDim.x + threadIdx.x;
    if (e >= E) return;
    int src = ei[e];
    int dst = ei[E + e];
    g_csr[g_exc[dst] + g_base[dst >> 10] + g_rank[e]] = src;
}

// ---------------------------------------------------------------------------
// K4: gather-sum, warp per node; resets g_deg for the next call
// ---------------------------------------------------------------------------
__global__ void gather_kernel(const float4* __restrict__ x4, int N) {
    int node = blockIdx.x * 8 + (threadIdx.x >> 5);
    int lane = threadIdx.x & 31;
    if (node >= N) return;

    int deg = g_deg[node];
    int j   = g_exc[node] + g_base[node >> 10];
    int end = j + deg;

    float4 acc = x4[(size_t)node * 32 + lane];
    for (; j + 1 < end; j += 2) {
        int s0 = g_csr[j];
        int s1 = g_csr[j + 1];
        float4 a = x4[(size_t)s0 * 32 + lane];
        float4 b = x4[(size_t)s1 * 32 + lane];
        acc.x += a.x; acc.y += a.y; acc.z += a.z; acc.w += a.w;
        acc.x += b.x; acc.y += b.y; acc.z += b.z; acc.w += b.w;
    }
    if (j < end) {
        float4 a = x4[(size_t)g_csr[j] * 32 + lane];
        acc.x += a.x; acc.y += a.y; acc.z += a.z; acc.w += a.w;
    }
    reinterpret_cast<float4*>(g_agg)[(size_t)node * 32 + lane] = acc;
    if (lane == 0) g_deg[node] = 0;     // ready for next call's hist
}

// ---------------------------------------------------------------------------
// K5: HMMA MLP. 256 threads / 8 warps tiled 4(m) x 2(n): warp owns 32x64.
// smem: b1s | b2s | Ah | Al | W1h | W1l | W2h | W2l
// ---------------------------------------------------------------------------
#define SM_AH   1024
#define SM_AL   (SM_AH  + TBYTES)
#define SM_W1H  (SM_AL  + TBYTES)
#define SM_W1L  (SM_W1H + TBYTES)
#define SM_W2H  (SM_W1L + TBYTES)
#define SM_W2L  (SM_W2H + TBYTES)
#define SM_TOT  (SM_W2L + TBYTES)

// acc layout: acc[im*8 + jn*2 + h][4]
__device__ __forceinline__ void do_gemm(const uint32_t aH[2], const uint32_t aL[2],
                                        uint32_t wH, uint32_t wL,
                                        float (*acc)[4]) {
    #pragma unroll
    for (int k = 0; k < 8; k++) {
        uint32_t ah[2][4], al[2][4];
        #pragma unroll
        for (int im = 0; im < 2; im++) {
            ldmx4(aH[im] + k * 32, ah[im]);
            ldmx4(aL[im] + k * 32, al[im]);
        }
        #pragma unroll
        for (int jn = 0; jn < 4; jn++) {
            uint32_t boff = (uint32_t)(jn * 16 * PA * 2 + k * 32);
            uint32_t bh[4], bl[4];
            ldmx4(wH + boff, bh);
            ldmx4(wL + boff, bl);
            #pragma unroll
            for (int im = 0; im < 2; im++) {
                float* c0 = acc[im * 8 + jn * 2];
                float* c1 = acc[im * 8 + jn * 2 + 1];
                mma16816(c0, ah[im], bh[0], bh[1]);
                mma16816(c0, ah[im], bl[0], bl[1]);
                mma16816(c0, al[im], bh[0], bh[1]);
                mma16816(c1, ah[im], bh[2], bh[3]);
                mma16816(c1, ah[im], bl[2], bl[3]);
                mma16816(c1, al[im], bh[2], bh[3]);
            }
        }
    }
}

__global__ void __launch_bounds__(256, 1)
mlp_hmma_kernel(const float* __restrict__ b1,
                const float* __restrict__ b2,
                float* __restrict__ out, int M) {
    extern __shared__ unsigned char sm[];
    const uint32_t sb = smem_u32(sm);
    const int tid  = threadIdx.x;
    const int w    = tid >> 5;
    const int lane = tid & 31;
    const int wm   = w >> 1;          // 0..3
    const int wn   = w & 1;           // 0..1
    const int rowBase = blockIdx.x * TILE_M;

    float* b1s = reinterpret_cast<float*>(sm);
    float* b2s = reinterpret_cast<float*>(sm + 512);
    if (tid < DIM) {
        b1s[tid] = b1[tid];
        b2s[tid] = b2[tid];
    }

    // weight tiles (linear coalesced copy)
    {
        const uint4* s1h = reinterpret_cast<const uint4*>(g_w1h);
        const uint4* s1l = reinterpret_cast<const uint4*>(g_w1l);
        const uint4* s2h = reinterpret_cast<const uint4*>(g_w2h);
        const uint4* s2l = reinterpret_cast<const uint4*>(g_w2l);
        uint4* d1h = reinterpret_cast<uint4*>(sm + SM_W1H);
        uint4* d1l = reinterpret_cast<uint4*>(sm + SM_W1L);
        uint4* d2h = reinterpret_cast<uint4*>(sm + SM_W2H);
        uint4* d2l = reinterpret_cast<uint4*>(sm + SM_W2L);
        for (int i = tid; i < TBYTES / 16; i += 256) {
            d1h[i] = s1h[i]; d1l[i] = s1l[i];
            d2h[i] = s2h[i]; d2l[i] = s2l[i];
        }
    }

    // A tile: load agg rows, split bf16 hi/lo, [m][k] pitch PA
    {
        __nv_bfloat16* Ah = reinterpret_cast<__nv_bfloat16*>(sm + SM_AH);
        __nv_bfloat16* Al = reinterpret_cast<__nv_bfloat16*>(sm + SM_AL);
        const float4* in4 = reinterpret_cast<const float4*>(g_agg);
        #pragma unroll
        for (int i = tid; i < TILE_M * 32; i += 256) {
            int m = i >> 5, c = i & 31;
            int gm = rowBase + m;
            float4 v = make_float4(0.f, 0.f, 0.f, 0.f);
            if (gm < M) v = in4[(size_t)gm * 32 + c];
            float vv[4] = {v.x, v.y, v.z, v.w};
            #pragma unroll
            for (int j = 0; j < 4; j++) {
                __nv_bfloat16 h, l;
                bf16_split(vv[j], h, l);
                Ah[m * PA + c * 4 + j] = h;
                Al[m * PA + c * 4 + j] = l;
            }
        }
    }
    __syncthreads();

    // ldmatrix lane addressing
    uint32_t aH[2], aL[2];
    #pragma unroll
    for (int im = 0; im < 2; im++) {
        uint32_t off = (uint32_t)(((wm * 32 + im * 16 + (lane & 15)) * PA
                                   + ((lane >> 4) << 3)) * 2);
        aH[im] = sb + SM_AH + off;
        aL[im] = sb + SM_AL + off;
    }
    const uint32_t bLaneOff =
        (uint32_t)((((lane & 7) + ((lane >> 4) << 3) + wn * 64) * PA
                    + (((lane >> 3) & 1) << 3)) * 2);

    float acc[16][4];
    #pragma unroll
    for (int i = 0; i < 16; i++)
        #pragma unroll
        for (int j = 0; j < 4; j++) acc[i][j] = 0.f;

    // ---- GEMM1 ----
    do_gemm(aH, aL, sb + SM_W1H + bLaneOff, sb + SM_W1L + bLaneOff, acc);

    // ---- epilogue 1: +b1, relu, split -> H into Ah/Al ----
    {
        __nv_bfloat16* Ah = reinterpret_cast<__nv_bfloat16*>(sm + SM_AH);
        __nv_bfloat16* Al = reinterpret_cast<__nv_bfloat16*>(sm + SM_AL);
        #pragma unroll
        for (int im = 0; im < 2; im++) {
            int r0 = wm * 32 + im * 16 + (lane >> 2);
            int r1 = r0 + 8;
            #pragma unroll
            for (int jn = 0; jn < 4; jn++) {
                #pragma unroll
                for (int h = 0; h < 2; h++) {
                    float* c = acc[im * 8 + jn * 2 + h];
                    int n = wn * 64 + jn * 16 + h * 8 + 2 * (lane & 3);
                    float f00 = c[0] + b1s[n];
                    float f01 = c[1] + b1s[n + 1];
                    float f10 = c[2] + b1s[n];
                    float f11 = c[3] + b1s[n + 1];
                    f00 = f00 > 0.f ? f00 : 0.f;  f01 = f01 > 0.f ? f01 : 0.f;
                    f10 = f10 > 0.f ? f10 : 0.f;  f11 = f11 > 0.f ? f11 : 0.f;
                    __nv_bfloat16 hh, ll;
                    bf16_split(f00, hh, ll); Ah[r0*PA + n]   = hh; Al[r0*PA + n]   = ll;
                    bf16_split(f01, hh, ll); Ah[r0*PA + n+1] = hh; Al[r0*PA + n+1] = ll;
                    bf16_split(f10, hh, ll); Ah[r1*PA + n]   = hh; Al[r1*PA + n]   = ll;
                    bf16_split(f11, hh, ll); Ah[r1*PA + n+1] = hh; Al[r1*PA + n+1] = ll;
                    c[0] = c[1] = c[2] = c[3] = 0.f;
                }
            }
        }
    }
    __syncthreads();   // H cols of a row written by both n-warps

    // ---- GEMM2 ----
    do_gemm(aH, aL, sb + SM_W2H + bLaneOff, sb + SM_W2L + bLaneOff, acc);

    // ---- epilogue 2: +b2, store fp32 ----
    #pragma unroll
    for (int im = 0; im < 2; im++) {
        int gm0 = rowBase + wm * 32 + im * 16 + (lane >> 2);
        int gm1 = gm0 + 8;
        #pragma unroll
        for (int jn = 0; jn < 4; jn++) {
            #pragma unroll
            for (int h = 0; h < 2; h++) {
                float* c = acc[im * 8 + jn * 2 + h];
                int n = wn * 64 + jn * 16 + h * 8 + 2 * (lane & 3);
                if (gm0 < M) {
                    float2 o = make_float2(c[0] + b2s[n], c[1] + b2s[n + 1]);
                    *reinterpret_cast<float2*>(&out[(size_t)gm0 * DIM + n]) = o;
                }
                if (gm1 < M) {
                    float2 o = make_float2(c[2] + b2s[n], c[3] + b2s[n + 1]);
                    *reinterpret_cast<float2*>(&out[(size_t)gm1 * DIM + n]) = o;
                }
            }
        }
    }
}

// ---------------------------------------------------------------------------
// launch
// ---------------------------------------------------------------------------
extern "C" void kernel_launch(void* const* d_in, const int* in_sizes, int n_in,
                              void* d_out, int out_size) {
    const float* x   = (const float*)d_in[0];
    const int*   ei  = (const int*)d_in[1];
    const float* W1  = (const float*)d_in[2];
    const float* b1  = (const float*)d_in[3];
    const float* W2  = (const float*)d_in[4];
    const float* b2  = (const float*)d_in[5];
    float*       out = (float*)d_out;

    const int M = in_sizes[0] / DIM;   // 50000
    const int E = in_sizes[1] / 2;     // 640000
    const int nChunks = (M + 1023) / 1024;

    hist_kernel<<<(E + 255) / 256, 256>>>(ei, E, W1, W2);
    scan1_kernel<<<nChunks, 1024>>>(M, nChunks);
    fill_kernel<<<(E + 255) / 256, 256>>>(ei, E);
    gather_kernel<<<(M + 7) / 8, 256>>>(
        reinterpret_cast<const float4*>(x), M);

    cudaFuncSetAttribute(mlp_hmma_kernel,
                         cudaFuncAttributeMaxDynamicSharedMemorySize, SM_TOT);
    mlp_hmma_kernel<<<(M + TILE_M - 1) / TILE_M, 256, SM_TOT>>>(b1, b2, out, M);
}

// round 13
// speedup vs baseline: 1.7135x; 1.0049x over previous
#include <cuda_runtime.h>
#include <cuda_bf16.h>
#include <cstdint>

// ---------------------------------------------------------------------------
// GINConv: out = relu((x + segment_sum(x[src], dst)) @ W1 + b1) @ W2 + b2
// N=50000, E=640000, D=128, fp32, edge_index int32. 5 launches.
//
//   K1: hist   - deg histogram + per-edge rank (+ weight split, g_base zero)
//   K2: scan1  - per-chunk scan -> g_exc; chunk bases via atomics to g_base
//   K3: fill   - csr[g_exc[dst] + g_base[dst>>10] + rank[e]] = src
//   K4: gather - agg = x + sum x[csr], 4-way unrolled (MLP=4, 2 partials);
//                resets g_deg. Separate kernel ON PURPOSE (R10: fusing into
//                MLP -> 8 warps/SM, +57us).
//   K5: mlp    - HMMA bf16x3, 256 thr / 255 regs, 4(m)x2(n) warps
//                (512 thr spills, 2x regression: R7)
// ---------------------------------------------------------------------------

#define DIM    128
#define MAX_N  50000
#define MAX_E  640000
#define TILE_M 128
#define PA     136                       // padded pitch (elems), 272B rows
#define TBYTES (128 * PA * 2)            // 34816 B per bf16 tile

__device__ float g_agg[MAX_N * DIM];

__device__ int g_deg[MAX_N];             // zero-init at load; gather resets
__device__ int g_exc[MAX_N];
__device__ int g_base[64];
__device__ int g_rank[MAX_E];
__device__ int g_csr[MAX_E];

// W^T hi/lo tiles, [n][k] row-major, pitch PA
__device__ __align__(16) __nv_bfloat16 g_w1h[128 * PA];
__device__ __align__(16) __nv_bfloat16 g_w1l[128 * PA];
__device__ __align__(16) __nv_bfloat16 g_w2h[128 * PA];
__device__ __align__(16) __nv_bfloat16 g_w2l[128 * PA];

__device__ __forceinline__ uint32_t smem_u32(const void* p) {
    uint32_t a;
    asm("{ .reg .u64 t; cvta.to.shared.u64 t, %1; cvt.u32.u64 %0, t; }"
        : "=r"(a) : "l"(p));
    return a;
}
__device__ __forceinline__ void ldmx4(uint32_t addr, uint32_t r[4]) {
    asm volatile("ldmatrix.sync.aligned.m8n8.x4.shared.b16 {%0,%1,%2,%3}, [%4];"
                 : "=r"(r[0]), "=r"(r[1]), "=r"(r[2]), "=r"(r[3]) : "r"(addr));
}
__device__ __forceinline__ void mma16816(float c[4], const uint32_t a[4],
                                         uint32_t b0, uint32_t b1) {
    asm volatile("mma.sync.aligned.m16n8k16.row.col.f32.bf16.bf16.f32 "
                 "{%0,%1,%2,%3}, {%4,%5,%6,%7}, {%8,%9}, {%0,%1,%2,%3};"
                 : "+f"(c[0]), "+f"(c[1]), "+f"(c[2]), "+f"(c[3])
                 : "r"(a[0]), "r"(a[1]), "r"(a[2]), "r"(a[3]), "r"(b0), "r"(b1));
}
__device__ __forceinline__ void bf16_split(float a, __nv_bfloat16& h, __nv_bfloat16& l) {
    h = __float2bfloat16_rn(a);
    l = __float2bfloat16_rn(a - __bfloat162float(h));
}
__device__ __forceinline__ void f4add(float4& a, const float4 b) {
    a.x += b.x; a.y += b.y; a.z += b.z; a.w += b.w;
}

// ---------------------------------------------------------------------------
// K1: hist + weight prep + g_base zero
// ---------------------------------------------------------------------------
__global__ void hist_kernel(const int* __restrict__ ei, int E,
                            const float* __restrict__ W1,
                            const float* __restrict__ W2) {
    int e = blockIdx.x * blockDim.x + threadIdx.x;
    if (e < DIM * DIM) {
        int k = e >> 7, n = e & 127;
        int o = n * PA + k;
        __nv_bfloat16 h, l;
        bf16_split(W1[e], h, l);
        g_w1h[o] = h; g_w1l[o] = l;
        bf16_split(W2[e], h, l);
        g_w2h[o] = h; g_w2l[o] = l;
    }
    if (e < 64) g_base[e] = 0;
    if (e < E) g_rank[e] = atomicAdd(&g_deg[ei[E + e]], 1);
}

// ---------------------------------------------------------------------------
// K2: per-chunk scan -> g_exc; chunk totals broadcast via atomics to g_base
// ---------------------------------------------------------------------------
__global__ void scan1_kernel(int N, int nChunks) {
    __shared__ int s[1024];
    int tid = threadIdx.x;
    int idx = blockIdx.x * 1024 + tid;
    int v = (idx < N) ? g_deg[idx] : 0;
    s[tid] = v;
    __syncthreads();
    #pragma unroll
    for (int off = 1; off < 1024; off <<= 1) {
        int t = (tid >= off) ? s[tid - off] : 0;
        __syncthreads();
        s[tid] += t;
        __syncthreads();
    }
    if (idx < N) g_exc[idx] = s[tid] - v;          // exclusive within chunk
    if (tid == 1023) {
        int tot = s[1023];
        for (int c = blockIdx.x + 1; c < nChunks; c++)
            atomicAdd(&g_base[c], tot);
    }
}

// ---------------------------------------------------------------------------
// K3: CSR fill (atomic-free)
// ---------------------------------------------------------------------------
__global__ void fill_kernel(const int* __restrict__ ei, int E) {
    int e = blockIdx.x * blockDim.x + threadIdx.x;
    if (e >= E) return;
    int src = ei[e];
    int dst = ei[E + e];
    g_csr[g_exc[dst] + g_base[dst >> 10] + g_rank[e]] = src;
}

// ---------------------------------------------------------------------------
// K4: gather-sum, warp per node, 4-way unrolled; resets g_deg
// ---------------------------------------------------------------------------
__global__ void gather_kernel(const float4* __restrict__ x4, int N) {
    int node = blockIdx.x * 8 + (threadIdx.x >> 5);
    int lane = threadIdx.x & 31;
    if (node >= N) return;

    int deg = g_deg[node];
    int j   = g_exc[node] + g_base[node >> 10];
    int end = j + deg;

    float4 acc0 = x4[(size_t)node * 32 + lane];
    float4 acc1 = make_float4(0.f, 0.f, 0.f, 0.f);

    for (; j + 3 < end; j += 4) {
        int s0 = g_csr[j];
        int s1 = g_csr[j + 1];
        int s2 = g_csr[j + 2];
        int s3 = g_csr[j + 3];
        float4 a = x4[(size_t)s0 * 32 + lane];
        float4 b = x4[(size_t)s1 * 32 + lane];
        float4 c = x4[(size_t)s2 * 32 + lane];
        float4 d = x4[(size_t)s3 * 32 + lane];
        f4add(acc0, a);
        f4add(acc1, b);
        f4add(acc0, c);
        f4add(acc1, d);
    }
    if (j + 1 < end) {
        int s0 = g_csr[j];
        int s1 = g_csr[j + 1];
        float4 a = x4[(size_t)s0 * 32 + lane];
        float4 b = x4[(size_t)s1 * 32 + lane];
        f4add(acc0, a);
        f4add(acc1, b);
        j += 2;
    }
    if (j < end) {
        float4 a = x4[(size_t)g_csr[j] * 32 + lane];
        f4add(acc0, a);
    }
    f4add(acc0, acc1);
    reinterpret_cast<float4*>(g_agg)[(size_t)node * 32 + lane] = acc0;
    if (lane == 0) g_deg[node] = 0;     // ready for next call's hist
}

// ---------------------------------------------------------------------------
// K5: HMMA MLP. 256 threads / 8 warps tiled 4(m) x 2(n): warp owns 32x64.
// smem: b1s | b2s | Ah | Al | W1h | W1l | W2h | W2l
// ---------------------------------------------------------------------------
#define SM_AH   1024
#define SM_AL   (SM_AH  + TBYTES)
#define SM_W1H  (SM_AL  + TBYTES)
#define SM_W1L  (SM_W1H + TBYTES)
#define SM_W2H  (SM_W1L + TBYTES)
#define SM_W2L  (SM_W2H + TBYTES)
#define SM_TOT  (SM_W2L + TBYTES)

// acc layout: acc[im*8 + jn*2 + h][4]
__device__ __forceinline__ void do_gemm(const uint32_t aH[2], const uint32_t aL[2],
                                        uint32_t wH, uint32_t wL,
                                        float (*acc)[4]) {
    #pragma unroll
    for (int k = 0; k < 8; k++) {
        uint32_t ah[2][4], al[2][4];
        #pragma unroll
        for (int im = 0; im < 2; im++) {
            ldmx4(aH[im] + k * 32, ah[im]);
            ldmx4(aL[im] + k * 32, al[im]);
        }
        #pragma unroll
        for (int jn = 0; jn < 4; jn++) {
            uint32_t boff = (uint32_t)(jn * 16 * PA * 2 + k * 32);
            uint32_t bh[4], bl[4];
            ldmx4(wH + boff, bh);
            ldmx4(wL + boff, bl);
            #pragma unroll
            for (int im = 0; im < 2; im++) {
                float* c0 = acc[im * 8 + jn * 2];
                float* c1 = acc[im * 8 + jn * 2 + 1];
                mma16816(c0, ah[im], bh[0], bh[1]);
                mma16816(c0, ah[im], bl[0], bl[1]);
                mma16816(c0, al[im], bh[0], bh[1]);
                mma16816(c1, ah[im], bh[2], bh[3]);
                mma16816(c1, ah[im], bl[2], bl[3]);
                mma16816(c1, al[im], bh[2], bh[3]);
            }
        }
    }
}

__global__ void __launch_bounds__(256, 1)
mlp_hmma_kernel(const float* __restrict__ b1,
                const float* __restrict__ b2,
                float* __restrict__ out, int M) {
    extern __shared__ unsigned char sm[];
    const uint32_t sb = smem_u32(sm);
    const int tid  = threadIdx.x;
    const int w    = tid >> 5;
    const int lane = tid & 31;
    const int wm   = w >> 1;          // 0..3
    const int wn   = w & 1;           // 0..1
    const int rowBase = blockIdx.x * TILE_M;

    float* b1s = reinterpret_cast<float*>(sm);
    float* b2s = reinterpret_cast<float*>(sm + 512);
    if (tid < DIM) {
        b1s[tid] = b1[tid];
        b2s[tid] = b2[tid];
    }

    // weight tiles (linear coalesced copy)
    {
        const uint4* s1h = reinterpret_cast<const uint4*>(g_w1h);
        const uint4* s1l = reinterpret_cast<const uint4*>(g_w1l);
        const uint4* s2h = reinterpret_cast<const uint4*>(g_w2h);
        const uint4* s2l = reinterpret_cast<const uint4*>(g_w2l);
        uint4* d1h = reinterpret_cast<uint4*>(sm + SM_W1H);
        uint4* d1l = reinterpret_cast<uint4*>(sm + SM_W1L);
        uint4* d2h = reinterpret_cast<uint4*>(sm + SM_W2H);
        uint4* d2l = reinterpret_cast<uint4*>(sm + SM_W2L);
        for (int i = tid; i < TBYTES / 16; i += 256) {
            d1h[i] = s1h[i]; d1l[i] = s1l[i];
            d2h[i] = s2h[i]; d2l[i] = s2l[i];
        }
    }

    // A tile: load agg rows, split bf16 hi/lo, [m][k] pitch PA
    {
        __nv_bfloat16* Ah = reinterpret_cast<__nv_bfloat16*>(sm + SM_AH);
        __nv_bfloat16* Al = reinterpret_cast<__nv_bfloat16*>(sm + SM_AL);
        const float4* in4 = reinterpret_cast<const float4*>(g_agg);
        #pragma unroll
        for (int i = tid; i < TILE_M * 32; i += 256) {
            int m = i >> 5, c = i & 31;
            int gm = rowBase + m;
            float4 v = make_float4(0.f, 0.f, 0.f, 0.f);
            if (gm < M) v = in4[(size_t)gm * 32 + c];
            float vv[4] = {v.x, v.y, v.z, v.w};
            #pragma unroll
            for (int j = 0; j < 4; j++) {
                __nv_bfloat16 h, l;
                bf16_split(vv[j], h, l);
                Ah[m * PA + c * 4 + j] = h;
                Al[m * PA + c * 4 + j] = l;
            }
        }
    }
    __syncthreads();

    // ldmatrix lane addressing
    uint32_t aH[2], aL[2];
    #pragma unroll
    for (int im = 0; im < 2; im++) {
        uint32_t off = (uint32_t)(((wm * 32 + im * 16 + (lane & 15)) * PA
                                   + ((lane >> 4) << 3)) * 2);
        aH[im] = sb + SM_AH + off;
        aL[im] = sb + SM_AL + off;
    }
    const uint32_t bLaneOff =
        (uint32_t)((((lane & 7) + ((lane >> 4) << 3) + wn * 64) * PA
                    + (((lane >> 3) & 1) << 3)) * 2);

    float acc[16][4];
    #pragma unroll
    for (int i = 0; i < 16; i++)
        #pragma unroll
        for (int j = 0; j < 4; j++) acc[i][j] = 0.f;

    // ---- GEMM1 ----
    do_gemm(aH, aL, sb + SM_W1H + bLaneOff, sb + SM_W1L + bLaneOff, acc);

    // ---- epilogue 1: +b1, relu, split -> H into Ah/Al ----
    {
        __nv_bfloat16* Ah = reinterpret_cast<__nv_bfloat16*>(sm + SM_AH);
        __nv_bfloat16* Al = reinterpret_cast<__nv_bfloat16*>(sm + SM_AL);
        #pragma unroll
        for (int im = 0; im < 2; im++) {
            int r0 = wm * 32 + im * 16 + (lane >> 2);
            int r1 = r0 + 8;
            #pragma unroll
            for (int jn = 0; jn < 4; jn++) {
                #pragma unroll
                for (int h = 0; h < 2; h++) {
                    float* c = acc[im * 8 + jn * 2 + h];
                    int n = wn * 64 + jn * 16 + h * 8 + 2 * (lane & 3);
                    float f00 = c[0] + b1s[n];
                    float f01 = c[1] + b1s[n + 1];
                    float f10 = c[2] + b1s[n];
                    float f11 = c[3] + b1s[n + 1];
                    f00 = f00 > 0.f ? f00 : 0.f;  f01 = f01 > 0.f ? f01 : 0.f;
                    f10 = f10 > 0.f ? f10 : 0.f;  f11 = f11 > 0.f ? f11 : 0.f;
                    __nv_bfloat16 hh, ll;
                    bf16_split(f00, hh, ll); Ah[r0*PA + n]   = hh; Al[r0*PA + n]   = ll;
                    bf16_split(f01, hh, ll); Ah[r0*PA + n+1] = hh; Al[r0*PA + n+1] = ll;
                    bf16_split(f10, hh, ll); Ah[r1*PA + n]   = hh; Al[r1*PA + n]   = ll;
                    bf16_split(f11, hh, ll); Ah[r1*PA + n+1] = hh; Al[r1*PA + n+1] = ll;
                    c[0] = c[1] = c[2] = c[3] = 0.f;
                }
            }
        }
    }
    __syncthreads();   // H cols of a row written by both n-warps

    // ---- GEMM2 ----
    do_gemm(aH, aL, sb + SM_W2H + bLaneOff, sb + SM_W2L + bLaneOff, acc);

    // ---- epilogue 2: +b2, store fp32 ----
    #pragma unroll
    for (int im = 0; im < 2; im++) {
        int gm0 = rowBase + wm * 32 + im * 16 + (lane >> 2);
        int gm1 = gm0 + 8;
        #pragma unroll
        for (int jn = 0; jn < 4; jn++) {
            #pragma unroll
            for (int h = 0; h < 2; h++) {
                float* c = acc[im * 8 + jn * 2 + h];
                int n = wn * 64 + jn * 16 + h * 8 + 2 * (lane & 3);
                if (gm0 < M) {
                    float2 o = make_float2(c[0] + b2s[n], c[1] + b2s[n + 1]);
                    *reinterpret_cast<float2*>(&out[(size_t)gm0 * DIM + n]) = o;
                }
                if (gm1 < M) {
                    float2 o = make_float2(c[2] + b2s[n], c[3] + b2s[n + 1]);
                    *reinterpret_cast<float2*>(&out[(size_t)gm1 * DIM + n]) = o;
                }
            }
        }
    }
}

// ---------------------------------------------------------------------------
// launch
// ---------------------------------------------------------------------------
extern "C" void kernel_launch(void* const* d_in, const int* in_sizes, int n_in,
                              void* d_out, int out_size) {
    const float* x   = (const float*)d_in[0];
    const int*   ei  = (const int*)d_in[1];
    const float* W1  = (const float*)d_in[2];
    const float* b1  = (const float*)d_in[3];
    const float* W2  = (const float*)d_in[4];
    const float* b2  = (const float*)d_in[5];
    float*       out = (float*)d_out;

    const int M = in_sizes[0] / DIM;   // 50000
    const int E = in_sizes[1] / 2;     // 640000
    const int nChunks = (M + 1023) / 1024;

    hist_kernel<<<(E + 255) / 256, 256>>>(ei, E, W1, W2);
    scan1_kernel<<<nChunks, 1024>>>(M, nChunks);
    fill_kernel<<<(E + 255) / 256, 256>>>(ei, E);
    gather_kernel<<<(M + 7) / 8, 256>>>(
        reinterpret_cast<const float4*>(x), M);

    cudaFuncSetAttribute(mlp_hmma_kernel,
                         cudaFuncAttributeMaxDynamicSharedMemorySize, SM_TOT);
    mlp_hmma_kernel<<<(M + TILE_M - 1) / TILE_M, 256, SM_TOT>>>(b1, b2, out, M);
}

// round 14
// speedup vs baseline: 1.7312x; 1.0103x over previous
#include <cuda_runtime.h>
#include <cuda_bf16.h>
#include <cstdint>

// ---------------------------------------------------------------------------
// GINConv: out = relu((x + segment_sum(x[src], dst)) @ W1 + b1) @ W2 + b2
// N=50000, E=640000, D=128, fp32, edge_index int32. 5 launches.
//
//   K1: hist   - deg histogram + per-edge rank (+ weight split, g_base zero)
//   K2: scan1  - per-chunk scan -> g_exc; chunk bases via atomics to g_base
//   K3: fill   - csr[g_exc[dst] + g_base[dst>>10] + rank[e]] = src
//   K4: gather - agg = x + sum x[csr] (plateau at ~28us; L2/L1tex bound;
//                two tuning attempts neutral -> leave alone). Separate
//                kernel ON PURPOSE (R10: fusing into MLP +57us).
//   K5: mlp    - PERSISTENT HMMA bf16x3: one block per SM loads weight
//                tiles once, loops over row tiles. 256 thr / 255 regs,
//                4(m)x2(n) warps (512 thr spills: R7).
// ---------------------------------------------------------------------------

#define DIM    128
#define MAX_N  50000
#define MAX_E  640000
#define TILE_M 128
#define PA     136                       // padded pitch (elems), 272B rows
#define TBYTES (128 * PA * 2)            // 34816 B per bf16 tile

__device__ float g_agg[MAX_N * DIM];

__device__ int g_deg[MAX_N];             // zero-init at load; gather resets
__device__ int g_exc[MAX_N];
__device__ int g_base[64];
__device__ int g_rank[MAX_E];
__device__ int g_csr[MAX_E];

// W^T hi/lo tiles, [n][k] row-major, pitch PA
__device__ __align__(16) __nv_bfloat16 g_w1h[128 * PA];
__device__ __align__(16) __nv_bfloat16 g_w1l[128 * PA];
__device__ __align__(16) __nv_bfloat16 g_w2h[128 * PA];
__device__ __align__(16) __nv_bfloat16 g_w2l[128 * PA];

__device__ __forceinline__ uint32_t smem_u32(const void* p) {
    uint32_t a;
    asm("{ .reg .u64 t; cvta.to.shared.u64 t, %1; cvt.u32.u64 %0, t; }"
        : "=r"(a) : "l"(p));
    return a;
}
__device__ __forceinline__ void ldmx4(uint32_t addr, uint32_t r[4]) {
    asm volatile("ldmatrix.sync.aligned.m8n8.x4.shared.b16 {%0,%1,%2,%3}, [%4];"
                 : "=r"(r[0]), "=r"(r[1]), "=r"(r[2]), "=r"(r[3]) : "r"(addr));
}
__device__ __forceinline__ void mma16816(float c[4], const uint32_t a[4],
                                         uint32_t b0, uint32_t b1) {
    asm volatile("mma.sync.aligned.m16n8k16.row.col.f32.bf16.bf16.f32 "
                 "{%0,%1,%2,%3}, {%4,%5,%6,%7}, {%8,%9}, {%0,%1,%2,%3};"
                 : "+f"(c[0]), "+f"(c[1]), "+f"(c[2]), "+f"(c[3])
                 : "r"(a[0]), "r"(a[1]), "r"(a[2]), "r"(a[3]), "r"(b0), "r"(b1));
}
__device__ __forceinline__ void bf16_split(float a, __nv_bfloat16& h, __nv_bfloat16& l) {
    h = __float2bfloat16_rn(a);
    l = __float2bfloat16_rn(a - __bfloat162float(h));
}
__device__ __forceinline__ void f4add(float4& a, const float4 b) {
    a.x += b.x; a.y += b.y; a.z += b.z; a.w += b.w;
}

// ---------------------------------------------------------------------------
// K1: hist + weight prep + g_base zero
// ---------------------------------------------------------------------------
__global__ void hist_kernel(const int* __restrict__ ei, int E,
                            const float* __restrict__ W1,
                            const float* __restrict__ W2) {
    int e = blockIdx.x * blockDim.x + threadIdx.x;
    if (e < DIM * DIM) {
        int k = e >> 7, n = e & 127;
        int o = n * PA + k;
        __nv_bfloat16 h, l;
        bf16_split(W1[e], h, l);
        g_w1h[o] = h; g_w1l[o] = l;
        bf16_split(W2[e], h, l);
        g_w2h[o] = h; g_w2l[o] = l;
    }
    if (e < 64) g_base[e] = 0;
    if (e < E) g_rank[e] = atomicAdd(&g_deg[ei[E + e]], 1);
}

// ---------------------------------------------------------------------------
// K2: per-chunk scan -> g_exc; chunk totals broadcast via atomics to g_base
// ---------------------------------------------------------------------------
__global__ void scan1_kernel(int N, int nChunks) {
    __shared__ int s[1024];
    int tid = threadIdx.x;
    int idx = blockIdx.x * 1024 + tid;
    int v = (idx < N) ? g_deg[idx] : 0;
    s[tid] = v;
    __syncthreads();
    #pragma unroll
    for (int off = 1; off < 1024; off <<= 1) {
        int t = (tid >= off) ? s[tid - off] : 0;
        __syncthreads();
        s[tid] += t;
        __syncthreads();
    }
    if (idx < N) g_exc[idx] = s[tid] - v;          // exclusive within chunk
    if (tid == 1023) {
        int tot = s[1023];
        for (int c = blockIdx.x + 1; c < nChunks; c++)
            atomicAdd(&g_base[c], tot);
    }
}

// ---------------------------------------------------------------------------
// K3: CSR fill (atomic-free)
// ---------------------------------------------------------------------------
__global__ void fill_kernel(const int* __restrict__ ei, int E) {
    int e = blockIdx.x * blockDim.x + threadIdx.x;
    if (e >= E) return;
    int src = ei[e];
    int dst = ei[E + e];
    g_csr[g_exc[dst] + g_base[dst >> 10] + g_rank[e]] = src;
}

// ---------------------------------------------------------------------------
// K4: gather-sum, warp per node, 4-way unrolled; resets g_deg
// ---------------------------------------------------------------------------
__global__ void gather_kernel(const float4* __restrict__ x4, int N) {
    int node = blockIdx.x * 8 + (threadIdx.x >> 5);
    int lane = threadIdx.x & 31;
    if (node >= N) return;

    int deg = g_deg[node];
    int j   = g_exc[node] + g_base[node >> 10];
    int end = j + deg;

    float4 acc0 = x4[(size_t)node * 32 + lane];
    float4 acc1 = make_float4(0.f, 0.f, 0.f, 0.f);

    for (; j + 3 < end; j += 4) {
        int s0 = g_csr[j];
        int s1 = g_csr[j + 1];
        int s2 = g_csr[j + 2];
        int s3 = g_csr[j + 3];
        float4 a = x4[(size_t)s0 * 32 + lane];
        float4 b = x4[(size_t)s1 * 32 + lane];
        float4 c = x4[(size_t)s2 * 32 + lane];
        float4 d = x4[(size_t)s3 * 32 + lane];
        f4add(acc0, a);
        f4add(acc1, b);
        f4add(acc0, c);
        f4add(acc1, d);
    }
    if (j + 1 < end) {
        int s0 = g_csr[j];
        int s1 = g_csr[j + 1];
        float4 a = x4[(size_t)s0 * 32 + lane];
        float4 b = x4[(size_t)s1 * 32 + lane];
        f4add(acc0, a);
        f4add(acc1, b);
        j += 2;
    }
    if (j < end) {
        float4 a = x4[(size_t)g_csr[j] * 32 + lane];
        f4add(acc0, a);
    }
    f4add(acc0, acc1);
    reinterpret_cast<float4*>(g_agg)[(size_t)node * 32 + lane] = acc0;
    if (lane == 0) g_deg[node] = 0;     // ready for next call's hist
}

// ---------------------------------------------------------------------------
// K5: PERSISTENT HMMA MLP. One block per SM; weights loaded once; loop tiles.
// 256 threads / 8 warps tiled 4(m) x 2(n): warp owns 32x64.
// smem: b1s | b2s | Ah | Al | W1h | W1l | W2h | W2l
// ---------------------------------------------------------------------------
#define SM_AH   1024
#define SM_AL   (SM_AH  + TBYTES)
#define SM_W1H  (SM_AL  + TBYTES)
#define SM_W1L  (SM_W1H + TBYTES)
#define SM_W2H  (SM_W1L + TBYTES)
#define SM_W2L  (SM_W2H + TBYTES)
#define SM_TOT  (SM_W2L + TBYTES)

// acc layout: acc[im*8 + jn*2 + h][4]
__device__ __forceinline__ void do_gemm(const uint32_t aH[2], const uint32_t aL[2],
                                        uint32_t wH, uint32_t wL,
                                        float (*acc)[4]) {
    #pragma unroll
    for (int k = 0; k < 8; k++) {
        uint32_t ah[2][4], al[2][4];
        #pragma unroll
        for (int im = 0; im < 2; im++) {
            ldmx4(aH[im] + k * 32, ah[im]);
            ldmx4(aL[im] + k * 32, al[im]);
        }
        #pragma unroll
        for (int jn = 0; jn < 4; jn++) {
            uint32_t boff = (uint32_t)(jn * 16 * PA * 2 + k * 32);
            uint32_t bh[4], bl[4];
            ldmx4(wH + boff, bh);
            ldmx4(wL + boff, bl);
            #pragma unroll
            for (int im = 0; im < 2; im++) {
                float* c0 = acc[im * 8 + jn * 2];
                float* c1 = acc[im * 8 + jn * 2 + 1];
                mma16816(c0, ah[im], bh[0], bh[1]);
                mma16816(c0, ah[im], bl[0], bl[1]);
                mma16816(c0, al[im], bh[0], bh[1]);
                mma16816(c1, ah[im], bh[2], bh[3]);
                mma16816(c1, ah[im], bl[2], bl[3]);
                mma16816(c1, al[im], bh[2], bh[3]);
            }
        }
    }
}

__global__ void __launch_bounds__(256, 1)
mlp_hmma_kernel(const float* __restrict__ b1,
                const float* __restrict__ b2,
                float* __restrict__ out, int M, int nTiles) {
    extern __shared__ unsigned char sm[];
    const uint32_t sb = smem_u32(sm);
    const int tid  = threadIdx.x;
    const int w    = tid >> 5;
    const int lane = tid & 31;
    const int wm   = w >> 1;          // 0..3
    const int wn   = w & 1;           // 0..1

    float* b1s = reinterpret_cast<float*>(sm);
    float* b2s = reinterpret_cast<float*>(sm + 512);
    if (tid < DIM) {
        b1s[tid] = b1[tid];
        b2s[tid] = b2[tid];
    }

    // weight tiles: loaded ONCE per persistent block
    {
        const uint4* s1h = reinterpret_cast<const uint4*>(g_w1h);
        const uint4* s1l = reinterpret_cast<const uint4*>(g_w1l);
        const uint4* s2h = reinterpret_cast<const uint4*>(g_w2h);
        const uint4* s2l = reinterpret_cast<const uint4*>(g_w2l);
        uint4* d1h = reinterpret_cast<uint4*>(sm + SM_W1H);
        uint4* d1l = reinterpret_cast<uint4*>(sm + SM_W1L);
        uint4* d2h = reinterpret_cast<uint4*>(sm + SM_W2H);
        uint4* d2l = reinterpret_cast<uint4*>(sm + SM_W2L);
        for (int i = tid; i < TBYTES / 16; i += 256) {
            d1h[i] = s1h[i]; d1l[i] = s1l[i];
            d2h[i] = s2h[i]; d2l[i] = s2l[i];
        }
    }

    // fixed ldmatrix lane addressing
    uint32_t aH[2], aL[2];
    #pragma unroll
    for (int im = 0; im < 2; im++) {
        uint32_t off = (uint32_t)(((wm * 32 + im * 16 + (lane & 15)) * PA
                                   + ((lane >> 4) << 3)) * 2);
        aH[im] = sb + SM_AH + off;
        aL[im] = sb + SM_AL + off;
    }
    const uint32_t bLaneOff =
        (uint32_t)((((lane & 7) + ((lane >> 4) << 3) + wn * 64) * PA
                    + (((lane >> 3) & 1) << 3)) * 2);
    const uint32_t w1H = sb + SM_W1H + bLaneOff;
    const uint32_t w1L = sb + SM_W1L + bLaneOff;
    const uint32_t w2H = sb + SM_W2H + bLaneOff;
    const uint32_t w2L = sb + SM_W2L + bLaneOff;

    for (int t = blockIdx.x; t < nTiles; t += gridDim.x) {
        const int rowBase = t * TILE_M;

        __syncthreads();   // prior tile's GEMM2 reads of Ah/Al must be done

        // A tile: load agg rows, split bf16 hi/lo, [m][k] pitch PA
        {
            __nv_bfloat16* Ah = reinterpret_cast<__nv_bfloat16*>(sm + SM_AH);
            __nv_bfloat16* Al = reinterpret_cast<__nv_bfloat16*>(sm + SM_AL);
            const float4* in4 = reinterpret_cast<const float4*>(g_agg);
            #pragma unroll
            for (int i = tid; i < TILE_M * 32; i += 256) {
                int m = i >> 5, c = i & 31;
                int gm = rowBase + m;
                float4 v = make_float4(0.f, 0.f, 0.f, 0.f);
                if (gm < M) v = in4[(size_t)gm * 32 + c];
                float vv[4] = {v.x, v.y, v.z, v.w};
                #pragma unroll
                for (int j = 0; j < 4; j++) {
                    __nv_bfloat16 h, l;
                    bf16_split(vv[j], h, l);
                    Ah[m * PA + c * 4 + j] = h;
                    Al[m * PA + c * 4 + j] = l;
                }
            }
        }
        __syncthreads();

        float acc[16][4];
        #pragma unroll
        for (int i = 0; i < 16; i++)
            #pragma unroll
            for (int j = 0; j < 4; j++) acc[i][j] = 0.f;

        // ---- GEMM1 ----
        do_gemm(aH, aL, w1H, w1L, acc);

        // ---- epilogue 1: +b1, relu, split -> H into Ah/Al ----
        {
            __nv_bfloat16* Ah = reinterpret_cast<__nv_bfloat16*>(sm + SM_AH);
            __nv_bfloat16* Al = reinterpret_cast<__nv_bfloat16*>(sm + SM_AL);
            #pragma unroll
            for (int im = 0; im < 2; im++) {
                int r0 = wm * 32 + im * 16 + (lane >> 2);
                int r1 = r0 + 8;
                #pragma unroll
                for (int jn = 0; jn < 4; jn++) {
                    #pragma unroll
                    for (int h = 0; h < 2; h++) {
                        float* c = acc[im * 8 + jn * 2 + h];
                        int n = wn * 64 + jn * 16 + h * 8 + 2 * (lane & 3);
                        float f00 = c[0] + b1s[n];
                        float f01 = c[1] + b1s[n + 1];
                        float f10 = c[2] + b1s[n];
                        float f11 = c[3] + b1s[n + 1];
                        f00 = f00 > 0.f ? f00 : 0.f;  f01 = f01 > 0.f ? f01 : 0.f;
                        f10 = f10 > 0.f ? f10 : 0.f;  f11 = f11 > 0.f ? f11 : 0.f;
                        __nv_bfloat16 hh, ll;
                        bf16_split(f00, hh, ll); Ah[r0*PA + n]   = hh; Al[r0*PA + n]   = ll;
                        bf16_split(f01, hh, ll); Ah[r0*PA + n+1] = hh; Al[r0*PA + n+1] = ll;
                        bf16_split(f10, hh, ll); Ah[r1*PA + n]   = hh; Al[r1*PA + n]   = ll;
                        bf16_split(f11, hh, ll); Ah[r1*PA + n+1] = hh; Al[r1*PA + n+1] = ll;
                        c[0] = c[1] = c[2] = c[3] = 0.f;
                    }
                }
            }
        }
        __syncthreads();   // H cols of a row written by both n-warps

        // ---- GEMM2 ----
        do_gemm(aH, aL, w2H, w2L, acc);

        // ---- epilogue 2: +b2, store fp32 ----
        #pragma unroll
        for (int im = 0; im < 2; im++) {
            int gm0 = rowBase + wm * 32 + im * 16 + (lane >> 2);
            int gm1 = gm0 + 8;
            #pragma unroll
            for (int jn = 0; jn < 4; jn++) {
                #pragma unroll
                for (int h = 0; h < 2; h++) {
                    float* c = acc[im * 8 + jn * 2 + h];
                    int n = wn * 64 + jn * 16 + h * 8 + 2 * (lane & 3);
                    if (gm0 < M) {
                        float2 o = make_float2(c[0] + b2s[n], c[1] + b2s[n + 1]);
                        *reinterpret_cast<float2*>(&out[(size_t)gm0 * DIM + n]) = o;
                    }
                    if (gm1 < M) {
                        float2 o = make_float2(c[2] + b2s[n], c[3] + b2s[n + 1]);
                        *reinterpret_cast<float2*>(&out[(size_t)gm1 * DIM + n]) = o;
                    }
                }
            }
        }
    }
}

// ---------------------------------------------------------------------------
// launch
// ---------------------------------------------------------------------------
extern "C" void kernel_launch(void* const* d_in, const int* in_sizes, int n_in,
                              void* d_out, int out_size) {
    const float* x   = (const float*)d_in[0];
    const int*   ei  = (const int*)d_in[1];
    const float* W1  = (const float*)d_in[2];
    const float* b1  = (const float*)d_in[3];
    const float* W2  = (const float*)d_in[4];
    const float* b2  = (const float*)d_in[5];
    float*       out = (float*)d_out;

    const int M = in_sizes[0] / DIM;   // 50000
    const int E = in_sizes[1] / 2;     // 640000
    const int nChunks = (M + 1023) / 1024;
    const int nTiles  = (M + TILE_M - 1) / TILE_M;

    hist_kernel<<<(E + 255) / 256, 256>>>(ei, E, W1, W2);
    scan1_kernel<<<nChunks, 1024>>>(M, nChunks);
    fill_kernel<<<(E + 255) / 256, 256>>>(ei, E);
    gather_kernel<<<(M + 7) / 8, 256>>>(
        reinterpret_cast<const float4*>(x), M);

    int sms = 148;
    cudaDeviceGetAttribute(&sms, cudaDevAttrMultiProcessorCount, 0);
    int grid = sms < nTiles ? sms : nTiles;

    cudaFuncSetAttribute(mlp_hmma_kernel,
                         cudaFuncAttributeMaxDynamicSharedMemorySize, SM_TOT);
    mlp_hmma_kernel<<<grid, 256, SM_TOT>>>(b1, b2, out, M, nTiles);
}